// round 15
// baseline (speedup 1.0000x reference)
#include <cuda_runtime.h>
#include <cuda_fp16.h>
#include <math.h>
#include <stdint.h>

#define Bsz   16
#define ANCH  1614
#define TOPN  6
#define PADC  224
#define C_IN  2048
#define P1    196
#define OC    128
#define K1    18432
#define N1    3136
#define SPLK  9
#define RSTR  304          // padded rows per image (256 grid + 48 guard)

// ---------------- device scratch ----------------
__device__ float   g_part1[SPLK][OC][N1];
__device__ __half  g_wr[9*OC*C_IN];           // W per-tap [tap][oc][ic], single fp16 limb
__device__ __half  g_rp[Bsz*RSTR*C_IN];       // padded activations, single fp16 limb
__device__ float   g_d1[Bsz*OC*P1];
__device__ float   g2_part[8][OC][Bsz*64];
__device__ float   g_d2[Bsz*OC*49];
__device__ float   g3_part[8][OC][Bsz*16];
__device__ float   g_d3[Bsz*OC*16];
__device__ int     g_topidx[Bsz*TOPN];

// ---------------- helpers ----------------
__device__ __forceinline__ uint32_t smem_u32(const void* p) {
    uint32_t a;
    asm("{ .reg .u64 t; cvta.to.shared.u64 t, %1; cvt.u32.u64 %0, t; }" : "=r"(a) : "l"(p));
    return a;
}
__device__ __forceinline__ void ldsm4(uint32_t* r, uint32_t addr) {
    asm volatile("ldmatrix.sync.aligned.m8n8.x4.shared.b16 {%0,%1,%2,%3}, [%4];"
                 : "=r"(r[0]), "=r"(r[1]), "=r"(r[2]), "=r"(r[3]) : "r"(addr));
}
__device__ __forceinline__ void mma_f16(float* c, const uint32_t* a, uint32_t b0, uint32_t b1) {
    asm volatile(
        "mma.sync.aligned.m16n8k16.row.col.f32.f16.f16.f32 "
        "{%0,%1,%2,%3}, {%4,%5,%6,%7}, {%8,%9}, {%0,%1,%2,%3};"
        : "+f"(c[0]), "+f"(c[1]), "+f"(c[2]), "+f"(c[3])
        : "r"(a[0]), "r"(a[1]), "r"(a[2]), "r"(a[3]), "r"(b0), "r"(b1));
}
#define CPA(dst, src) \
    asm volatile("cp.async.cg.shared.global [%0], [%1], 16;" \
        :: "r"(dst), "l"(src) : "memory")
#define CPA_COMMIT() asm volatile("cp.async.commit_group;" ::: "memory")
#define CPA_WAIT0()  asm volatile("cp.async.wait_group 0;" ::: "memory")

// ---------------- prep kernels ----------------
__global__ void k_wtap(const float* __restrict__ w) {
    int ic = blockIdx.x * 256 + threadIdx.x;
    int oc = blockIdx.y;
    const float* src = w + (size_t)oc * K1 + (size_t)ic * 9;
    float v[9];
#pragma unroll
    for (int r = 0; r < 9; ++r) v[r] = src[r];
#pragma unroll
    for (int r = 0; r < 9; ++r)
        g_wr[((size_t)r * OC + oc) * C_IN + ic] = __float2half_rn(v[r]);
}

// zero-fill all pad rows of the padded activation grid
__global__ void k_rzero(void) {
    size_t i = (size_t)blockIdx.x * 256 + threadIdx.x;   // uint4 index
    size_t tot = (size_t)Bsz * RSTR * C_IN / 8;
    if (i >= tot) return;
    size_t elem = i * 8;
    int rowg = (int)(elem / C_IN);
    int row  = rowg % RSTR;
    int y = row >> 4, x = row & 15;
    bool pad = (row >= 256) || (y == 0) || (y == 15) || (x == 0) || (x == 15);
    if (pad) ((uint4*)g_rp)[i] = make_uint4(0, 0, 0, 0);
}

// transpose interior: input [b][ic][196] -> padded [b][(y+1)*16+(x+1)][ic]
__global__ void k_rT(const float* __restrict__ r) {
    __shared__ float tile[32][33];
    const int b   = blockIdx.z;
    const int ic0 = blockIdx.y * 32;
    const int p0  = blockIdx.x * 32;
    const int tx  = threadIdx.x;
    const int ty  = threadIdx.y;
    const float* src = r + ((size_t)b * C_IN + ic0) * P1 + p0;
#pragma unroll
    for (int i = 0; i < 4; ++i) {
        int icr = ty + i * 8;
        int p = p0 + tx;
        tile[icr][tx] = (p < P1) ? src[icr * P1 + tx] : 0.f;
    }
    __syncthreads();
#pragma unroll
    for (int i = 0; i < 4; ++i) {
        int p  = p0 + ty + i * 8;
        int ic = ic0 + tx;
        if (p < P1) {
            float v = tile[tx][ty + i * 8];
            int prow = ((p / 14) + 1) * 16 + (p % 14) + 1;
            g_rp[((size_t)b * RSTR + prow) * C_IN + ic] = __float2half_rn(v);
        }
    }
}

// ---------------- conv1: padded-B tap-reuse fp16 single-limb mma.sync GEMM ----------
// grid (16 images, 9 splits), 512 threads, BM=128 BN=256, 1 CTA/SM.
// unit u = (blk,tap); 64 units per split in 16 QUADS (one sync per quad).
// A 8-stage buffered (1 limb); B single-limb, double-buffered per 32-ic block.
#define A_ROWB 80
#define A_STG  10240          // 128 rows * 80, 1 limb
#define B_BASE 81920          // after 8 A stages
#define B_ROWS 296
#define B_STG  23680          // 296 * 80, single limb
#define CONV1_SMEM (B_BASE + 2*B_STG)   // 129280

__global__ __launch_bounds__(512, 1)
void conv1_mma(void)
{
    extern __shared__ __align__(256) char sm[];
    const uint32_t smb = smem_u32(sm);
    const int tid  = threadIdx.x;
    const int wid  = tid >> 5;
    const int lane = tid & 31;
    const int bImg = blockIdx.x;        // image 0..15
    const int spl  = blockIdx.y;        // 0..8

    const int u0   = spl * 64;
    const int uend = u0 + 64;
    const int lastBlk = (uend - 1) / 9;

    // ---- A cp.async mapping: 512 threads x 16B = 8KB payload ----
    const int rowA = tid >> 2;
    const int qA   = tid & 3;
    const uint32_t aOff = (uint32_t)(rowA * A_ROWB + qA * 16);

    // ---- ldmatrix base addresses ----
    const int wm = wid & 3;
    const int wn = wid >> 2;
    const uint32_t aLd = smb + (uint32_t)((wm * 32 + (lane & 15)) * A_ROWB + (lane >> 4) * 16);
    const uint32_t bLd = smb + B_BASE +
        (uint32_t)((wn * 64 + (lane & 7) + ((lane >> 4) & 1) * 8) * A_ROWB + ((lane >> 3) & 1) * 16);

    float acc[2][8][4];
#pragma unroll
    for (int mi = 0; mi < 2; ++mi)
#pragma unroll
        for (int j = 0; j < 8; ++j)
#pragma unroll
            for (int q = 0; q < 4; ++q) acc[mi][j][q] = 0.f;

    auto issueA = [&](int tap, int blk, int stage) {
        const size_t srcIdx = (((size_t)tap * OC + rowA) * C_IN) + blk * 32 + qA * 8;
        CPA(smb + (uint32_t)stage * A_STG + aOff, g_wr + srcIdx);
    };
    auto issueB = [&](int blk, int stage) {
        const uint32_t base = smb + B_BASE + (uint32_t)stage * B_STG;
        const size_t gbase = (size_t)bImg * RSTR * C_IN + blk * 32;
#pragma unroll
        for (int i = 0; i < 3; ++i) {
            int op = tid + i * 512;
            if (op < B_ROWS * 4) {
                int row = op >> 2;
                int q   = op & 3;
                CPA(base + row * A_ROWB + q * 16, g_rp + gbase + (size_t)row * C_IN + q * 8);
            }
        }
    };

    // compute one tap-unit (1 product: a*b)
    auto computeU = [&](int tap, int blk, int astage) {
        const int ky = (tap >= 6) ? 2 : ((tap >= 3) ? 1 : 0);
        const uint32_t delta = (uint32_t)(tap + ky * 13) * A_ROWB;   // (ky*16+kx)*80
        const uint32_t aCur = (uint32_t)astage * A_STG;
        const uint32_t bCur = (uint32_t)(blk & 1) * B_STG;
#pragma unroll
        for (int kf = 0; kf < 2; ++kf) {
            uint32_t ah[2][4];
            ldsm4(ah[0], aLd + aCur + kf * 32);
            ldsm4(ah[1], aLd + aCur + kf * 32 + 16 * A_ROWB);
#pragma unroll
            for (int jp = 0; jp < 4; ++jp) {
                uint32_t bh[4];
                ldsm4(bh, bLd + bCur + delta + jp * (16 * A_ROWB) + kf * 32);
                mma_f16(acc[0][jp*2],   ah[0], bh[0], bh[1]);
                mma_f16(acc[0][jp*2+1], ah[0], bh[2], bh[3]);
                mma_f16(acc[1][jp*2],   ah[1], bh[0], bh[1]);
                mma_f16(acc[1][jp*2+1], ah[1], bh[2], bh[3]);
            }
        }
    };

    // --- prologue: B(blk0) [+B(blk0+1) if tap4 passed], A(u0..u0+3) ---
    const int blk0 = u0 / 9;
    const int tap0 = u0 - blk0 * 9;
    issueB(blk0, blk0 & 1);
    if (tap0 > 4 && blk0 + 1 <= lastBlk) issueB(blk0 + 1, (blk0 + 1) & 1);
    {
        int tj = tap0, bj = blk0;
#pragma unroll
        for (int j = 0; j < 4; ++j) {
            issueA(tj, bj, (u0 + j) & 7);
            if (++tj == 9) { tj = 0; ++bj; }
        }
    }
    CPA_COMMIT();

    // A issue cursor at u0+4
    int tc = tap0 + 4, bc = blk0;
    if (tc >= 9) { tc -= 9; ++bc; }

    int tapu = tap0, blku = blk0;
    for (int p = 0; p < 16; ++p) {
        const int u = u0 + 4 * p;
        CPA_WAIT0();
        __syncthreads();

        bool any = false;
#pragma unroll
        for (int j = 0; j < 4; ++j) {
            if (u + 4 + j < uend) {
                issueA(tc, bc, (u + 4 + j) & 7);
                if (++tc == 9) { tc = 0; ++bc; }
                any = true;
            }
        }
        // if this quad contains tap4 of its block, stage B(blk+1)
        {
            int tq = tapu, bq = blku;
#pragma unroll
            for (int j = 0; j < 4; ++j) {
                if (tq == 4 && bq + 1 <= lastBlk) {
                    issueB(bq + 1, (bq + 1) & 1);
                    any = true;
                }
                if (++tq == 9) { tq = 0; ++bq; }
            }
        }
        if (any) CPA_COMMIT();

        // compute the four units of this quad
#pragma unroll
        for (int j = 0; j < 4; ++j) {
            computeU(tapu, blku, (u + j) & 7);
            if (++tapu == 9) { tapu = 0; ++blku; }
        }
    }

    // ---------- epilogue: padded cols -> valid output positions ----------
#pragma unroll
    for (int mi = 0; mi < 2; ++mi) {
        const int r0 = wm * 32 + mi * 16 + (lane >> 2);
#pragma unroll
        for (int j = 0; j < 8; ++j) {
            const int c0 = wn * 64 + j * 8 + (lane & 3) * 2;
            const int oy = c0 >> 4;
            const int ox = c0 & 15;
            if (oy < 14) {
                if (ox < 14) {
                    int n = bImg * 196 + oy * 14 + ox;
                    g_part1[spl][r0][n]     = acc[mi][j][0];
                    g_part1[spl][r0 + 8][n] = acc[mi][j][2];
                }
                if (ox + 1 < 14) {
                    int n = bImg * 196 + oy * 14 + ox + 1;
                    g_part1[spl][r0][n]     = acc[mi][j][1];
                    g_part1[spl][r0 + 8][n] = acc[mi][j][3];
                }
            }
        }
    }
}

__global__ void conv1_finish(const float* __restrict__ bias)
{
    int i = blockIdx.x * 256 + threadIdx.x;   // float4 index
    if (i >= OC * N1 / 4) return;
    int e  = i << 2;
    int oc = e / N1;
    int n  = e - oc * N1;
    float4 s = make_float4(0.f, 0.f, 0.f, 0.f);
    const float* base = &g_part1[0][0][0];
#pragma unroll
    for (int k = 0; k < SPLK; ++k) {
        float4 p = *(const float4*)(base + (size_t)k * OC * N1 + e);
        s.x += p.x; s.y += p.y; s.z += p.z; s.w += p.w;
    }
    float bb = bias[oc];
    s.x = fmaxf(s.x + bb, 0.f);
    s.y = fmaxf(s.y + bb, 0.f);
    s.z = fmaxf(s.z + bb, 0.f);
    s.w = fmaxf(s.w + bb, 0.f);
    int b = n / P1;
    int p = n - b * P1;
    *(float4*)&g_d1[(size_t)b * OC * P1 + oc * P1 + p] = s;
}

// ---------------- conv2: 128->128 3x3 s2 p1 (14->7), split-K GEMM ----------------
__global__ __launch_bounds__(256, 2)
void conv2_gemm(const float* __restrict__ w)
{
    __shared__ __align__(16) float As[16][128];
    __shared__ __align__(16) float Bs[16][64];

    const int b   = blockIdx.x;
    const int spl = blockIdx.y;
    const int tid = threadIdx.x;
    const int k0b = spl * 144;

    const int ocA = tid >> 1;
    const int khA = (tid & 1) * 8;
    const float* wA = w + (size_t)ocA * 1152 + khA;

    const int kkB = tid >> 4;
    const int nB  = (tid & 15) << 2;
    const float* src = g_d1 + (size_t)b * OC * P1;
    int noy[4], nox[4]; bool nok[4];
#pragma unroll
    for (int u = 0; u < 4; ++u) {
        int n = nB + u;
        nok[u] = n < 49;
        int nn = nok[u] ? n : 0;
        noy[u] = nn / 7;
        nox[u] = nn - (nn / 7) * 7;
    }

    const int tm4 = (tid & 15) << 2;
    const int tn4 = (tid >> 4) << 2;

    float acc[8][4];
#pragma unroll
    for (int i = 0; i < 8; ++i)
#pragma unroll
        for (int j = 0; j < 4; ++j) acc[i][j] = 0.f;

    for (int it = 0; it < 9; ++it) {
        int k0 = k0b + it * 16;
        float4 a0 = *(const float4*)(wA + k0);
        float4 a1 = *(const float4*)(wA + k0 + 4);
        float bv[4];
        {
            int k  = k0 + kkB;
            int ic = k / 9;
            int r  = k - ic * 9;
            int ky = r / 3;
            int kx = r - ky * 3;
#pragma unroll
            for (int u = 0; u < 4; ++u) {
                int iy = 2 * noy[u] + ky - 1;
                int ix = 2 * nox[u] + kx - 1;
                bool ok = nok[u] && ((unsigned)iy < 14u) && ((unsigned)ix < 14u);
                bv[u] = ok ? __ldg(src + ic * P1 + iy * 14 + ix) : 0.f;
            }
        }
        __syncthreads();
        As[khA+0][ocA] = a0.x; As[khA+1][ocA] = a0.y;
        As[khA+2][ocA] = a0.z; As[khA+3][ocA] = a0.w;
        As[khA+4][ocA] = a1.x; As[khA+5][ocA] = a1.y;
        As[khA+6][ocA] = a1.z; As[khA+7][ocA] = a1.w;
        *(float4*)&Bs[kkB][nB] = make_float4(bv[0], bv[1], bv[2], bv[3]);
        __syncthreads();

#pragma unroll
        for (int kk = 0; kk < 16; ++kk) {
            float4 q0 = *(const float4*)&As[kk][tm4];
            float4 q1 = *(const float4*)&As[kk][64 + tm4];
            float4 bq = *(const float4*)&Bs[kk][tn4];
            float aa[8] = {q0.x, q0.y, q0.z, q0.w, q1.x, q1.y, q1.z, q1.w};
            float bb[4] = {bq.x, bq.y, bq.z, bq.w};
#pragma unroll
            for (int i = 0; i < 8; ++i)
#pragma unroll
                for (int j = 0; j < 4; ++j)
                    acc[i][j] += aa[i] * bb[j];
        }
    }

#pragma unroll
    for (int i = 0; i < 4; ++i) {
        float4 v0 = make_float4(acc[i][0],   acc[i][1],   acc[i][2],   acc[i][3]);
        float4 v1 = make_float4(acc[i+4][0], acc[i+4][1], acc[i+4][2], acc[i+4][3]);
        *(float4*)&g2_part[spl][tm4 + i     ][b * 64 + tn4] = v0;
        *(float4*)&g2_part[spl][64 + tm4 + i][b * 64 + tn4] = v1;
    }
}

__global__ void conv2_finish(const float* __restrict__ bias)
{
    int i = blockIdx.x * 256 + threadIdx.x;
    if (i >= Bsz * OC * 49) return;
    int b  = i / (OC * 49);
    int r  = i - b * (OC * 49);
    int oc = r / 49;
    int p  = r - oc * 49;
    float s = bias[oc];
#pragma unroll
    for (int k = 0; k < 8; ++k) s += g2_part[k][oc][b * 64 + p];
    g_d2[(size_t)b * OC * 49 + oc * 49 + p] = fmaxf(s, 0.f);
}

// ---------------- conv3: 128->128 3x3 s2 p1 (7->4), split-K GEMM ----------------
__global__ __launch_bounds__(256, 2)
void conv3_gemm(const float* __restrict__ w)
{
    __shared__ __align__(16) float As[16][128];
    __shared__ float Bs[16][16];

    const int b   = blockIdx.x;
    const int spl = blockIdx.y;
    const int tid = threadIdx.x;
    const int k0b = spl * 144;

    const int ocA = tid >> 1;
    const int khA = (tid & 1) * 8;
    const float* wA = w + (size_t)ocA * 1152 + khA;

    const int kkB = tid >> 4;
    const int nnB = tid & 15;
    const int oyB = nnB >> 2, oxB = nnB & 3;
    const float* src = g_d2 + (size_t)b * OC * 49;

    const int tm4 = (tid & 15) << 2;
    const int tn  = tid >> 4;

    float acc[8];
#pragma unroll
    for (int i = 0; i < 8; ++i) acc[i] = 0.f;

    for (int it = 0; it < 9; ++it) {
        int k0 = k0b + it * 16;
        float4 a0 = *(const float4*)(wA + k0);
        float4 a1 = *(const float4*)(wA + k0 + 4);
        float bv;
        {
            int k  = k0 + kkB;
            int ic = k / 9;
            int r  = k - ic * 9;
            int ky = r / 3;
            int kx = r - ky * 3;
            int iy = 2 * oyB + ky - 1;
            int ix = 2 * oxB + kx - 1;
            bool ok = ((unsigned)iy < 7u) && ((unsigned)ix < 7u);
            bv = ok ? __ldg(src + ic * 49 + iy * 7 + ix) : 0.f;
        }
        __syncthreads();
        As[khA+0][ocA] = a0.x; As[khA+1][ocA] = a0.y;
        As[khA+2][ocA] = a0.z; As[khA+3][ocA] = a0.w;
        As[khA+4][ocA] = a1.x; As[khA+5][ocA] = a1.y;
        As[khA+6][ocA] = a1.z; As[khA+7][ocA] = a1.w;
        Bs[kkB][nnB] = bv;
        __syncthreads();

#pragma unroll
        for (int kk = 0; kk < 16; ++kk) {
            float4 q0 = *(const float4*)&As[kk][tm4];
            float4 q1 = *(const float4*)&As[kk][64 + tm4];
            float bb = Bs[kk][tn];
            acc[0] += q0.x * bb; acc[1] += q0.y * bb;
            acc[2] += q0.z * bb; acc[3] += q0.w * bb;
            acc[4] += q1.x * bb; acc[5] += q1.y * bb;
            acc[6] += q1.z * bb; acc[7] += q1.w * bb;
        }
    }

#pragma unroll
    for (int i = 0; i < 4; ++i) {
        g3_part[spl][tm4 + i     ][b * 16 + tn] = acc[i];
        g3_part[spl][64 + tm4 + i][b * 16 + tn] = acc[i + 4];
    }
}

__global__ void conv3_finish(const float* __restrict__ bias)
{
    int i = blockIdx.x * 256 + threadIdx.x;
    if (i >= Bsz * OC * 16) return;
    int b  = i / (OC * 16);
    int r  = i - b * (OC * 16);
    int oc = r / 16;
    int p  = r - oc * 16;
    float s = bias[oc];
#pragma unroll
    for (int k = 0; k < 8; ++k) s += g3_part[k][oc][b * 16 + p];
    g_d3[(size_t)b * OC * 16 + oc * 16 + p] = fmaxf(s, 0.f);
}

// ---------------- tidy 1x1 convs -> rpn_score ----------------
__global__ void tidy_k(const float* __restrict__ w1, const float* __restrict__ b1,
                       const float* __restrict__ w2, const float* __restrict__ b2,
                       const float* __restrict__ w3, const float* __restrict__ b3,
                       float* __restrict__ out)
{
    int i = blockIdx.x * 256 + threadIdx.x;
    if (i >= Bsz * ANCH) return;
    int b = i / ANCH;
    int s = i - b * ANCH;

    const float* src; const float* wp; float bias; int p, stride;
    if (s < 1176) {
        int c = s / 196; p = s - c * 196;
        src = g_d1 + (size_t)b * OC * P1; stride = 196;
        wp = w1 + c * 128; bias = b1[c];
    } else if (s < 1470) {
        int ss = s - 1176; int c = ss / 49; p = ss - c * 49;
        src = g_d2 + (size_t)b * OC * 49; stride = 49;
        wp = w2 + c * 128; bias = b2[c];
    } else {
        int ss = s - 1470; int c = ss / 16; p = ss - c * 16;
        src = g_d3 + (size_t)b * OC * 16; stride = 16;
        wp = w3 + c * 128; bias = b3[c];
    }
    float a0 = 0.f, a1 = 0.f, a2 = 0.f, a3 = 0.f;
#pragma unroll 8
    for (int ic = 0; ic < 128; ic += 4) {
        a0 += src[(ic+0) * stride + p] * __ldg(wp + ic + 0);
        a1 += src[(ic+1) * stride + p] * __ldg(wp + ic + 1);
        a2 += src[(ic+2) * stride + p] * __ldg(wp + ic + 2);
        a3 += src[(ic+3) * stride + p] * __ldg(wp + ic + 3);
    }
    out[(size_t)b * ANCH + s] = bias + ((a0 + a1) + (a2 + a3));
}

// ---------------- hard NMS top-6 per batch ----------------
__global__ void nms_k(const float* __restrict__ scores, const int* __restrict__ anchors,
                      float* __restrict__ out_idx, float* __restrict__ out_prob)
{
    __shared__ float sc[ANCH];
    __shared__ float bx0[ANCH], bx1[ANCH], bx2[ANCH], bx3[ANCH];
    __shared__ float rv[256];
    __shared__ int   ri[256];
    __shared__ int   sel[TOPN];

    const int b = blockIdx.x, tid = threadIdx.x;
    for (int i = tid; i < ANCH; i += 256) {
        sc[i]  = scores[(size_t)b * ANCH + i];
        bx0[i] = (float)anchors[i * 4 + 0];
        bx1[i] = (float)anchors[i * 4 + 1];
        bx2[i] = (float)anchors[i * 4 + 2];
        bx3[i] = (float)anchors[i * 4 + 3];
    }
    __syncthreads();

    for (int t = 0; t < TOPN; ++t) {
        float bv = -INFINITY; int bi = ANCH;
        for (int i = tid; i < ANCH; i += 256) {
            float v = sc[i];
            if (v > bv) { bv = v; bi = i; }
        }
        rv[tid] = bv; ri[tid] = bi;
        __syncthreads();
        for (int s = 128; s > 0; s >>= 1) {
            if (tid < s) {
                float vo = rv[tid + s]; int io = ri[tid + s];
                if (vo > rv[tid] || (vo == rv[tid] && io < ri[tid])) {
                    rv[tid] = vo; ri[tid] = io;
                }
            }
            __syncthreads();
        }
        int j = ri[0];
        if (tid == 0) sel[t] = j;

        float by0 = bx0[j], by1 = bx1[j], by2 = bx2[j], by3 = bx3[j];
        float a1 = (by2 - by0) * (by3 - by1);
        for (int i = tid; i < ANCH; i += 256) {
            float yy0 = fmaxf(by0, bx0[i]);
            float xx0 = fmaxf(by1, bx1[i]);
            float yy1 = fminf(by2, bx2[i]);
            float xx1 = fminf(by3, bx3[i]);
            float inter = fmaxf(yy1 - yy0, 0.f) * fmaxf(xx1 - xx0, 0.f);
            float a2 = (bx2[i] - bx0[i]) * (bx3[i] - bx1[i]);
            float iou = inter / (a1 + a2 - inter);
            if (iou > 0.25f) sc[i] = -INFINITY;
        }
        __syncthreads();
    }

    if (tid < TOPN) {
        int j = sel[tid];
        out_idx[b * TOPN + tid]  = (float)j;
        out_prob[b * TOPN + tid] = scores[(size_t)b * ANCH + j];
        g_topidx[b * TOPN + tid] = j;
    }
}

// ---------------- bilinear crop-resize 224x224 ----------------
__global__ void crop_k(const float* __restrict__ x, const int* __restrict__ anchors,
                       float* __restrict__ out)
{
    const int crop = blockIdx.x;
    const int j    = blockIdx.y;
    const int i    = threadIdx.x;
    const int idx  = g_topidx[crop];
    const int y0 = anchors[idx * 4 + 0];
    const int x0 = anchors[idx * 4 + 1];
    const int y1 = anchors[idx * 4 + 2];
    const int x1 = anchors[idx * 4 + 3];

    float ty = (float)j / 223.f;
    float ys = (float)y0 + ty * (float)(y1 - y0 - 1);
    int   y0i = (int)floorf(ys);
    int   y1i = min(y0i + 1, 895);
    float wy  = ys - (float)y0i;

    float tx = (float)i / 223.f;
    float xs = (float)x0 + tx * (float)(x1 - x0 - 1);
    int   x0i = (int)floorf(xs);
    int   x1i = min(x0i + 1, 895);
    float wx  = xs - (float)x0i;

    int b  = crop / 6;
    int ya = y0i - PADC, yb = y1i - PADC;
    int xa = x0i - PADC, xb = x1i - PADC;
    bool vya = (unsigned)ya < 448u, vyb = (unsigned)yb < 448u;
    bool vxa = (unsigned)xa < 448u, vxb = (unsigned)xb < 448u;

#pragma unroll
    for (int c = 0; c < 3; ++c) {
        const float* img = x + ((size_t)(b * 3 + c)) * 448 * 448;
        float tl = (vya && vxa) ? __ldg(img + ya * 448 + xa) : 0.f;
        float tr = (vya && vxb) ? __ldg(img + ya * 448 + xb) : 0.f;
        float bl = (vyb && vxa) ? __ldg(img + yb * 448 + xa) : 0.f;
        float br = (vyb && vxb) ? __ldg(img + yb * 448 + xb) : 0.f;
        float v = tl * (1.f - wy) * (1.f - wx)
                + tr * (1.f - wy) * wx
                + bl * wy * (1.f - wx)
                + br * wy * wx;
        out[(((size_t)(crop * 3 + c)) * 224 + j) * 224 + i] = v;
    }
}

// ---------------- launch ----------------
extern "C" void kernel_launch(void* const* d_in, const int* in_sizes, int n_in,
                              void* d_out, int out_size)
{
    const float* x    = (const float*)d_in[0];
    const float* rpn  = (const float*)d_in[1];
    const int*   anch = (const int*)  d_in[2];
    const float* w1   = (const float*)d_in[3];
    const float* b1   = (const float*)d_in[4];
    const float* w2   = (const float*)d_in[5];
    const float* b2   = (const float*)d_in[6];
    const float* w3   = (const float*)d_in[7];
    const float* b3   = (const float*)d_in[8];
    const float* tw1  = (const float*)d_in[9];
    const float* tb1  = (const float*)d_in[10];
    const float* tw2  = (const float*)d_in[11];
    const float* tb2  = (const float*)d_in[12];
    const float* tw3  = (const float*)d_in[13];
    const float* tb3  = (const float*)d_in[14];
    float* out = (float*)d_out;

    const size_t OFF_IDX  = (size_t)Bsz * ANCH;
    const size_t OFF_PROB = OFF_IDX + Bsz * TOPN;
    const size_t OFF_IMG  = OFF_PROB + Bsz * TOPN;

    // prep (slots 1-3) -> conv1_mma at profiled slot 4
    k_wtap<<<dim3(8, 128), 256>>>(w1);
    k_rzero<<<(int)(((size_t)Bsz * RSTR * C_IN / 8 + 255) / 256), 256>>>();
    k_rT<<<dim3(7, 64, 16), dim3(32, 8)>>>(rpn);

    cudaFuncSetAttribute(conv1_mma, cudaFuncAttributeMaxDynamicSharedMemorySize,
                         CONV1_SMEM);
    conv1_mma<<<dim3(16, SPLK), 512, CONV1_SMEM>>>();
    conv1_finish<<<(OC * N1 / 4 + 255) / 256, 256>>>(b1);

    conv2_gemm<<<dim3(16, 8), 256>>>(w2);
    conv2_finish<<<(Bsz * OC * 49 + 255) / 256, 256>>>(b2);

    conv3_gemm<<<dim3(16, 8), 256>>>(w3);
    conv3_finish<<<(Bsz * OC * 16 + 255) / 256, 256>>>(b3);

    tidy_k<<<(Bsz * ANCH + 255) / 256, 256>>>(tw1, tb1, tw2, tb2, tw3, tb3, out);
    nms_k<<<Bsz, 256>>>(out, anch, out + OFF_IDX, out + OFF_PROB);
    crop_k<<<dim3(96, 224), 224>>>(x, anch, out + OFF_IMG);
}

// round 16
// speedup vs baseline: 1.4627x; 1.4627x over previous
#include <cuda_runtime.h>
#include <cuda_fp16.h>
#include <math.h>
#include <stdint.h>

#define Bsz   16
#define ANCH  1614
#define TOPN  6
#define PADC  224
#define C_IN  2048
#define P1    196
#define OC    128
#define K1    18432
#define N1    3136
#define SPLK  9
#define RSTR  304          // padded rows per image (256 grid + 48 guard)

// ---------------- device scratch ----------------
__device__ float   g_part1[SPLK][OC][N1];
__device__ __half  g_wr[9*OC*C_IN];           // W per-tap [tap][oc][ic], single fp16 limb
__device__ __half  g_rp[Bsz*RSTR*C_IN];       // padded activations, single fp16 limb
__device__ float   g_d1[Bsz*OC*P1];
__device__ float   g2_part[8][OC][Bsz*64];
__device__ float   g_d2[Bsz*OC*49];
__device__ float   g3_part[8][OC][Bsz*16];
__device__ float   g_d3[Bsz*OC*16];
__device__ int     g_topidx[Bsz*TOPN];

// ---------------- helpers ----------------
__device__ __forceinline__ uint32_t smem_u32(const void* p) {
    uint32_t a;
    asm("{ .reg .u64 t; cvta.to.shared.u64 t, %1; cvt.u32.u64 %0, t; }" : "=r"(a) : "l"(p));
    return a;
}
__device__ __forceinline__ void ldsm4(uint32_t* r, uint32_t addr) {
    asm volatile("ldmatrix.sync.aligned.m8n8.x4.shared.b16 {%0,%1,%2,%3}, [%4];"
                 : "=r"(r[0]), "=r"(r[1]), "=r"(r[2]), "=r"(r[3]) : "r"(addr));
}
__device__ __forceinline__ void mma_f16(float* c, const uint32_t* a, uint32_t b0, uint32_t b1) {
    asm volatile(
        "mma.sync.aligned.m16n8k16.row.col.f32.f16.f16.f32 "
        "{%0,%1,%2,%3}, {%4,%5,%6,%7}, {%8,%9}, {%0,%1,%2,%3};"
        : "+f"(c[0]), "+f"(c[1]), "+f"(c[2]), "+f"(c[3])
        : "r"(a[0]), "r"(a[1]), "r"(a[2]), "r"(a[3]), "r"(b0), "r"(b1));
}
#define CPA(dst, src) \
    asm volatile("cp.async.cg.shared.global [%0], [%1], 16;" \
        :: "r"(dst), "l"(src) : "memory")
#define CPA_COMMIT() asm volatile("cp.async.commit_group;" ::: "memory")
#define CPA_WAIT0()  asm volatile("cp.async.wait_group 0;" ::: "memory")

// ---------------- prep kernels ----------------
__global__ void k_wtap(const float* __restrict__ w) {
    int ic = blockIdx.x * 256 + threadIdx.x;
    int oc = blockIdx.y;
    const float* src = w + (size_t)oc * K1 + (size_t)ic * 9;
    float v[9];
#pragma unroll
    for (int r = 0; r < 9; ++r) v[r] = src[r];
#pragma unroll
    for (int r = 0; r < 9; ++r)
        g_wr[((size_t)r * OC + oc) * C_IN + ic] = __float2half_rn(v[r]);
}

// zero-fill all pad rows of the padded activation grid
__global__ void k_rzero(void) {
    size_t i = (size_t)blockIdx.x * 256 + threadIdx.x;   // uint4 index
    size_t tot = (size_t)Bsz * RSTR * C_IN / 8;
    if (i >= tot) return;
    size_t elem = i * 8;
    int rowg = (int)(elem / C_IN);
    int row  = rowg % RSTR;
    int y = row >> 4, x = row & 15;
    bool pad = (row >= 256) || (y == 0) || (y == 15) || (x == 0) || (x == 15);
    if (pad) ((uint4*)g_rp)[i] = make_uint4(0, 0, 0, 0);
}

// transpose interior: input [b][ic][196] -> padded [b][(y+1)*16+(x+1)][ic]
__global__ void k_rT(const float* __restrict__ r) {
    __shared__ float tile[32][33];
    const int b   = blockIdx.z;
    const int ic0 = blockIdx.y * 32;
    const int p0  = blockIdx.x * 32;
    const int tx  = threadIdx.x;
    const int ty  = threadIdx.y;
    const float* src = r + ((size_t)b * C_IN + ic0) * P1 + p0;
#pragma unroll
    for (int i = 0; i < 4; ++i) {
        int icr = ty + i * 8;
        int p = p0 + tx;
        tile[icr][tx] = (p < P1) ? src[icr * P1 + tx] : 0.f;
    }
    __syncthreads();
#pragma unroll
    for (int i = 0; i < 4; ++i) {
        int p  = p0 + ty + i * 8;
        int ic = ic0 + tx;
        if (p < P1) {
            float v = tile[tx][ty + i * 8];
            int prow = ((p / 14) + 1) * 16 + (p % 14) + 1;
            g_rp[((size_t)b * RSTR + prow) * C_IN + ic] = __float2half_rn(v);
        }
    }
}

// ---------------- conv1: padded-B tap-reuse fp16 single-limb mma.sync GEMM ----------
// grid (16 images, 9 splits), 512 threads, BM=128 BN=256, 1 CTA/SM.
// unit u = (blk,tap); 64 units per split in 16 QUADS (one sync per quad).
// A 8-stage buffered (1 limb); B single-limb, double-buffered per 32-ic block.
#define A_ROWB 80
#define A_STG  10240          // 128 rows * 80, 1 limb
#define B_BASE 81920          // after 8 A stages
#define B_ROWS 296
#define B_STG  23680          // 296 * 80, single limb
#define CONV1_SMEM (B_BASE + 2*B_STG)   // 129280

__global__ __launch_bounds__(512, 1)
void conv1_mma(void)
{
    extern __shared__ __align__(256) char sm[];
    const uint32_t smb = smem_u32(sm);
    const int tid  = threadIdx.x;
    const int wid  = tid >> 5;
    const int lane = tid & 31;
    const int bImg = blockIdx.x;        // image 0..15
    const int spl  = blockIdx.y;        // 0..8

    const int u0   = spl * 64;
    const int uend = u0 + 64;
    const int lastBlk = (uend - 1) / 9;

    // ---- A cp.async mapping: 512 threads x 16B = 8KB payload ----
    const int rowA = tid >> 2;
    const int qA   = tid & 3;
    const uint32_t aOff = (uint32_t)(rowA * A_ROWB + qA * 16);

    // ---- ldmatrix base addresses ----
    const int wm = wid & 3;
    const int wn = wid >> 2;
    const uint32_t aLd = smb + (uint32_t)((wm * 32 + (lane & 15)) * A_ROWB + (lane >> 4) * 16);
    const uint32_t bLd = smb + B_BASE +
        (uint32_t)((wn * 64 + (lane & 7) + ((lane >> 4) & 1) * 8) * A_ROWB + ((lane >> 3) & 1) * 16);

    float acc[2][8][4];
#pragma unroll
    for (int mi = 0; mi < 2; ++mi)
#pragma unroll
        for (int j = 0; j < 8; ++j)
#pragma unroll
            for (int q = 0; q < 4; ++q) acc[mi][j][q] = 0.f;

    auto issueA = [&](int tap, int blk, int stage) {
        const size_t srcIdx = (((size_t)tap * OC + rowA) * C_IN) + blk * 32 + qA * 8;
        CPA(smb + (uint32_t)stage * A_STG + aOff, g_wr + srcIdx);
    };
    auto issueB = [&](int blk, int stage) {
        const uint32_t base = smb + B_BASE + (uint32_t)stage * B_STG;
        const size_t gbase = (size_t)bImg * RSTR * C_IN + blk * 32;
#pragma unroll
        for (int i = 0; i < 3; ++i) {
            int op = tid + i * 512;
            if (op < B_ROWS * 4) {
                int row = op >> 2;
                int q   = op & 3;
                CPA(base + row * A_ROWB + q * 16, g_rp + gbase + (size_t)row * C_IN + q * 8);
            }
        }
    };

    // compute one tap-unit (1 product: a*b)
    auto computeU = [&](int tap, int blk, int astage) {
        const int ky = (tap >= 6) ? 2 : ((tap >= 3) ? 1 : 0);
        const uint32_t delta = (uint32_t)(tap + ky * 13) * A_ROWB;   // (ky*16+kx)*80
        const uint32_t aCur = (uint32_t)astage * A_STG;
        const uint32_t bCur = (uint32_t)(blk & 1) * B_STG;
#pragma unroll
        for (int kf = 0; kf < 2; ++kf) {
            uint32_t ah[2][4];
            ldsm4(ah[0], aLd + aCur + kf * 32);
            ldsm4(ah[1], aLd + aCur + kf * 32 + 16 * A_ROWB);
#pragma unroll
            for (int jp = 0; jp < 4; ++jp) {
                uint32_t bh[4];
                ldsm4(bh, bLd + bCur + delta + jp * (16 * A_ROWB) + kf * 32);
                mma_f16(acc[0][jp*2],   ah[0], bh[0], bh[1]);
                mma_f16(acc[0][jp*2+1], ah[0], bh[2], bh[3]);
                mma_f16(acc[1][jp*2],   ah[1], bh[0], bh[1]);
                mma_f16(acc[1][jp*2+1], ah[1], bh[2], bh[3]);
            }
        }
    };

    // --- prologue: B(blk0) [+B(blk0+1) if tap4 passed], A(u0..u0+3) ---
    const int blk0 = u0 / 9;
    const int tap0 = u0 - blk0 * 9;
    issueB(blk0, blk0 & 1);
    if (tap0 > 4 && blk0 + 1 <= lastBlk) issueB(blk0 + 1, (blk0 + 1) & 1);
    {
        int tj = tap0, bj = blk0;
#pragma unroll
        for (int j = 0; j < 4; ++j) {
            issueA(tj, bj, (u0 + j) & 7);
            if (++tj == 9) { tj = 0; ++bj; }
        }
    }
    CPA_COMMIT();

    // A issue cursor at u0+4
    int tc = tap0 + 4, bc = blk0;
    if (tc >= 9) { tc -= 9; ++bc; }

    int tapu = tap0, blku = blk0;
    for (int p = 0; p < 16; ++p) {
        const int u = u0 + 4 * p;
        CPA_WAIT0();
        __syncthreads();

        bool any = false;
#pragma unroll
        for (int j = 0; j < 4; ++j) {
            if (u + 4 + j < uend) {
                issueA(tc, bc, (u + 4 + j) & 7);
                if (++tc == 9) { tc = 0; ++bc; }
                any = true;
            }
        }
        // if this quad contains tap4 of its block, stage B(blk+1)
        {
            int tq = tapu, bq = blku;
#pragma unroll
            for (int j = 0; j < 4; ++j) {
                if (tq == 4 && bq + 1 <= lastBlk) {
                    issueB(bq + 1, (bq + 1) & 1);
                    any = true;
                }
                if (++tq == 9) { tq = 0; ++bq; }
            }
        }
        if (any) CPA_COMMIT();

        // compute the four units of this quad
#pragma unroll
        for (int j = 0; j < 4; ++j) {
            computeU(tapu, blku, (u + j) & 7);
            if (++tapu == 9) { tapu = 0; ++blku; }
        }
    }

    // ---------- epilogue: padded cols -> valid output positions ----------
#pragma unroll
    for (int mi = 0; mi < 2; ++mi) {
        const int r0 = wm * 32 + mi * 16 + (lane >> 2);
#pragma unroll
        for (int j = 0; j < 8; ++j) {
            const int c0 = wn * 64 + j * 8 + (lane & 3) * 2;
            const int oy = c0 >> 4;
            const int ox = c0 & 15;
            if (oy < 14) {
                if (ox < 14) {
                    int n = bImg * 196 + oy * 14 + ox;
                    g_part1[spl][r0][n]     = acc[mi][j][0];
                    g_part1[spl][r0 + 8][n] = acc[mi][j][2];
                }
                if (ox + 1 < 14) {
                    int n = bImg * 196 + oy * 14 + ox + 1;
                    g_part1[spl][r0][n]     = acc[mi][j][1];
                    g_part1[spl][r0 + 8][n] = acc[mi][j][3];
                }
            }
        }
    }
}

__global__ void conv1_finish(const float* __restrict__ bias)
{
    int i = blockIdx.x * 256 + threadIdx.x;   // float4 index
    if (i >= OC * N1 / 4) return;
    int e  = i << 2;
    int oc = e / N1;
    int n  = e - oc * N1;
    float4 s = make_float4(0.f, 0.f, 0.f, 0.f);
    const float* base = &g_part1[0][0][0];
#pragma unroll
    for (int k = 0; k < SPLK; ++k) {
        float4 p = *(const float4*)(base + (size_t)k * OC * N1 + e);
        s.x += p.x; s.y += p.y; s.z += p.z; s.w += p.w;
    }
    float bb = bias[oc];
    s.x = fmaxf(s.x + bb, 0.f);
    s.y = fmaxf(s.y + bb, 0.f);
    s.z = fmaxf(s.z + bb, 0.f);
    s.w = fmaxf(s.w + bb, 0.f);
    int b = n / P1;
    int p = n - b * P1;
    *(float4*)&g_d1[(size_t)b * OC * P1 + oc * P1 + p] = s;
}

// ---------------- conv2: 128->128 3x3 s2 p1 (14->7), split-K GEMM ----------------
__global__ __launch_bounds__(256, 2)
void conv2_gemm(const float* __restrict__ w)
{
    __shared__ __align__(16) float As[16][128];
    __shared__ __align__(16) float Bs[16][64];

    const int b   = blockIdx.x;
    const int spl = blockIdx.y;
    const int tid = threadIdx.x;
    const int k0b = spl * 144;

    const int ocA = tid >> 1;
    const int khA = (tid & 1) * 8;
    const float* wA = w + (size_t)ocA * 1152 + khA;

    const int kkB = tid >> 4;
    const int nB  = (tid & 15) << 2;
    const float* src = g_d1 + (size_t)b * OC * P1;
    int noy[4], nox[4]; bool nok[4];
#pragma unroll
    for (int u = 0; u < 4; ++u) {
        int n = nB + u;
        nok[u] = n < 49;
        int nn = nok[u] ? n : 0;
        noy[u] = nn / 7;
        nox[u] = nn - (nn / 7) * 7;
    }

    const int tm4 = (tid & 15) << 2;
    const int tn4 = (tid >> 4) << 2;

    float acc[8][4];
#pragma unroll
    for (int i = 0; i < 8; ++i)
#pragma unroll
        for (int j = 0; j < 4; ++j) acc[i][j] = 0.f;

    for (int it = 0; it < 9; ++it) {
        int k0 = k0b + it * 16;
        float4 a0 = *(const float4*)(wA + k0);
        float4 a1 = *(const float4*)(wA + k0 + 4);
        float bv[4];
        {
            int k  = k0 + kkB;
            int ic = k / 9;
            int r  = k - ic * 9;
            int ky = r / 3;
            int kx = r - ky * 3;
#pragma unroll
            for (int u = 0; u < 4; ++u) {
                int iy = 2 * noy[u] + ky - 1;
                int ix = 2 * nox[u] + kx - 1;
                bool ok = nok[u] && ((unsigned)iy < 14u) && ((unsigned)ix < 14u);
                bv[u] = ok ? __ldg(src + ic * P1 + iy * 14 + ix) : 0.f;
            }
        }
        __syncthreads();
        As[khA+0][ocA] = a0.x; As[khA+1][ocA] = a0.y;
        As[khA+2][ocA] = a0.z; As[khA+3][ocA] = a0.w;
        As[khA+4][ocA] = a1.x; As[khA+5][ocA] = a1.y;
        As[khA+6][ocA] = a1.z; As[khA+7][ocA] = a1.w;
        *(float4*)&Bs[kkB][nB] = make_float4(bv[0], bv[1], bv[2], bv[3]);
        __syncthreads();

#pragma unroll
        for (int kk = 0; kk < 16; ++kk) {
            float4 q0 = *(const float4*)&As[kk][tm4];
            float4 q1 = *(const float4*)&As[kk][64 + tm4];
            float4 bq = *(const float4*)&Bs[kk][tn4];
            float aa[8] = {q0.x, q0.y, q0.z, q0.w, q1.x, q1.y, q1.z, q1.w};
            float bb[4] = {bq.x, bq.y, bq.z, bq.w};
#pragma unroll
            for (int i = 0; i < 8; ++i)
#pragma unroll
                for (int j = 0; j < 4; ++j)
                    acc[i][j] += aa[i] * bb[j];
        }
    }

#pragma unroll
    for (int i = 0; i < 4; ++i) {
        float4 v0 = make_float4(acc[i][0],   acc[i][1],   acc[i][2],   acc[i][3]);
        float4 v1 = make_float4(acc[i+4][0], acc[i+4][1], acc[i+4][2], acc[i+4][3]);
        *(float4*)&g2_part[spl][tm4 + i     ][b * 64 + tn4] = v0;
        *(float4*)&g2_part[spl][64 + tm4 + i][b * 64 + tn4] = v1;
    }
}

__global__ void conv2_finish(const float* __restrict__ bias)
{
    int i = blockIdx.x * 256 + threadIdx.x;
    if (i >= Bsz * OC * 49) return;
    int b  = i / (OC * 49);
    int r  = i - b * (OC * 49);
    int oc = r / 49;
    int p  = r - oc * 49;
    float s = bias[oc];
#pragma unroll
    for (int k = 0; k < 8; ++k) s += g2_part[k][oc][b * 64 + p];
    g_d2[(size_t)b * OC * 49 + oc * 49 + p] = fmaxf(s, 0.f);
}

// ---------------- conv3: 128->128 3x3 s2 p1 (7->4), split-K GEMM ----------------
__global__ __launch_bounds__(256, 2)
void conv3_gemm(const float* __restrict__ w)
{
    __shared__ __align__(16) float As[16][128];
    __shared__ float Bs[16][16];

    const int b   = blockIdx.x;
    const int spl = blockIdx.y;
    const int tid = threadIdx.x;
    const int k0b = spl * 144;

    const int ocA = tid >> 1;
    const int khA = (tid & 1) * 8;
    const float* wA = w + (size_t)ocA * 1152 + khA;

    const int kkB = tid >> 4;
    const int nnB = tid & 15;
    const int oyB = nnB >> 2, oxB = nnB & 3;
    const float* src = g_d2 + (size_t)b * OC * 49;

    const int tm4 = (tid & 15) << 2;
    const int tn  = tid >> 4;

    float acc[8];
#pragma unroll
    for (int i = 0; i < 8; ++i) acc[i] = 0.f;

    for (int it = 0; it < 9; ++it) {
        int k0 = k0b + it * 16;
        float4 a0 = *(const float4*)(wA + k0);
        float4 a1 = *(const float4*)(wA + k0 + 4);
        float bv;
        {
            int k  = k0 + kkB;
            int ic = k / 9;
            int r  = k - ic * 9;
            int ky = r / 3;
            int kx = r - ky * 3;
            int iy = 2 * oyB + ky - 1;
            int ix = 2 * oxB + kx - 1;
            bool ok = ((unsigned)iy < 7u) && ((unsigned)ix < 7u);
            bv = ok ? __ldg(src + ic * 49 + iy * 7 + ix) : 0.f;
        }
        __syncthreads();
        As[khA+0][ocA] = a0.x; As[khA+1][ocA] = a0.y;
        As[khA+2][ocA] = a0.z; As[khA+3][ocA] = a0.w;
        As[khA+4][ocA] = a1.x; As[khA+5][ocA] = a1.y;
        As[khA+6][ocA] = a1.z; As[khA+7][ocA] = a1.w;
        Bs[kkB][nnB] = bv;
        __syncthreads();

#pragma unroll
        for (int kk = 0; kk < 16; ++kk) {
            float4 q0 = *(const float4*)&As[kk][tm4];
            float4 q1 = *(const float4*)&As[kk][64 + tm4];
            float bb = Bs[kk][tn];
            acc[0] += q0.x * bb; acc[1] += q0.y * bb;
            acc[2] += q0.z * bb; acc[3] += q0.w * bb;
            acc[4] += q1.x * bb; acc[5] += q1.y * bb;
            acc[6] += q1.z * bb; acc[7] += q1.w * bb;
        }
    }

#pragma unroll
    for (int i = 0; i < 4; ++i) {
        g3_part[spl][tm4 + i     ][b * 16 + tn] = acc[i];
        g3_part[spl][64 + tm4 + i][b * 16 + tn] = acc[i + 4];
    }
}

__global__ void conv3_finish(const float* __restrict__ bias)
{
    int i = blockIdx.x * 256 + threadIdx.x;
    if (i >= Bsz * OC * 16) return;
    int b  = i / (OC * 16);
    int r  = i - b * (OC * 16);
    int oc = r / 16;
    int p  = r - oc * 16;
    float s = bias[oc];
#pragma unroll
    for (int k = 0; k < 8; ++k) s += g3_part[k][oc][b * 16 + p];
    g_d3[(size_t)b * OC * 16 + oc * 16 + p] = fmaxf(s, 0.f);
}

// ---------------- tidy 1x1 convs -> rpn_score ----------------
__global__ void tidy_k(const float* __restrict__ w1, const float* __restrict__ b1,
                       const float* __restrict__ w2, const float* __restrict__ b2,
                       const float* __restrict__ w3, const float* __restrict__ b3,
                       float* __restrict__ out)
{
    int i = blockIdx.x * 256 + threadIdx.x;
    if (i >= Bsz * ANCH) return;
    int b = i / ANCH;
    int s = i - b * ANCH;

    const float* src; const float* wp; float bias; int p, stride;
    if (s < 1176) {
        int c = s / 196; p = s - c * 196;
        src = g_d1 + (size_t)b * OC * P1; stride = 196;
        wp = w1 + c * 128; bias = b1[c];
    } else if (s < 1470) {
        int ss = s - 1176; int c = ss / 49; p = ss - c * 49;
        src = g_d2 + (size_t)b * OC * 49; stride = 49;
        wp = w2 + c * 128; bias = b2[c];
    } else {
        int ss = s - 1470; int c = ss / 16; p = ss - c * 16;
        src = g_d3 + (size_t)b * OC * 16; stride = 16;
        wp = w3 + c * 128; bias = b3[c];
    }
    float a0 = 0.f, a1 = 0.f, a2 = 0.f, a3 = 0.f;
#pragma unroll 8
    for (int ic = 0; ic < 128; ic += 4) {
        a0 += src[(ic+0) * stride + p] * __ldg(wp + ic + 0);
        a1 += src[(ic+1) * stride + p] * __ldg(wp + ic + 1);
        a2 += src[(ic+2) * stride + p] * __ldg(wp + ic + 2);
        a3 += src[(ic+3) * stride + p] * __ldg(wp + ic + 3);
    }
    out[(size_t)b * ANCH + s] = bias + ((a0 + a1) + (a2 + a3));
}

// ---------------- hard NMS top-6 per batch ----------------
__global__ void nms_k(const float* __restrict__ scores, const int* __restrict__ anchors,
                      float* __restrict__ out_idx, float* __restrict__ out_prob)
{
    __shared__ float sc[ANCH];
    __shared__ float bx0[ANCH], bx1[ANCH], bx2[ANCH], bx3[ANCH];
    __shared__ float rv[256];
    __shared__ int   ri[256];
    __shared__ int   sel[TOPN];

    const int b = blockIdx.x, tid = threadIdx.x;
    for (int i = tid; i < ANCH; i += 256) {
        sc[i]  = scores[(size_t)b * ANCH + i];
        bx0[i] = (float)anchors[i * 4 + 0];
        bx1[i] = (float)anchors[i * 4 + 1];
        bx2[i] = (float)anchors[i * 4 + 2];
        bx3[i] = (float)anchors[i * 4 + 3];
    }
    __syncthreads();

    for (int t = 0; t < TOPN; ++t) {
        float bv = -INFINITY; int bi = ANCH;
        for (int i = tid; i < ANCH; i += 256) {
            float v = sc[i];
            if (v > bv) { bv = v; bi = i; }
        }
        rv[tid] = bv; ri[tid] = bi;
        __syncthreads();
        for (int s = 128; s > 0; s >>= 1) {
            if (tid < s) {
                float vo = rv[tid + s]; int io = ri[tid + s];
                if (vo > rv[tid] || (vo == rv[tid] && io < ri[tid])) {
                    rv[tid] = vo; ri[tid] = io;
                }
            }
            __syncthreads();
        }
        int j = ri[0];
        if (tid == 0) sel[t] = j;

        float by0 = bx0[j], by1 = bx1[j], by2 = bx2[j], by3 = bx3[j];
        float a1 = (by2 - by0) * (by3 - by1);
        for (int i = tid; i < ANCH; i += 256) {
            float yy0 = fmaxf(by0, bx0[i]);
            float xx0 = fmaxf(by1, bx1[i]);
            float yy1 = fminf(by2, bx2[i]);
            float xx1 = fminf(by3, bx3[i]);
            float inter = fmaxf(yy1 - yy0, 0.f) * fmaxf(xx1 - xx0, 0.f);
            float a2 = (bx2[i] - bx0[i]) * (bx3[i] - bx1[i]);
            float iou = inter / (a1 + a2 - inter);
            if (iou > 0.25f) sc[i] = -INFINITY;
        }
        __syncthreads();
    }

    if (tid < TOPN) {
        int j = sel[tid];
        out_idx[b * TOPN + tid]  = (float)j;
        out_prob[b * TOPN + tid] = scores[(size_t)b * ANCH + j];
        g_topidx[b * TOPN + tid] = j;
    }
}

// ---------------- bilinear crop-resize 224x224 ----------------
__global__ void crop_k(const float* __restrict__ x, const int* __restrict__ anchors,
                       float* __restrict__ out)
{
    const int crop = blockIdx.x;
    const int j    = blockIdx.y;
    const int i    = threadIdx.x;
    const int idx  = g_topidx[crop];
    const int y0 = anchors[idx * 4 + 0];
    const int x0 = anchors[idx * 4 + 1];
    const int y1 = anchors[idx * 4 + 2];
    const int x1 = anchors[idx * 4 + 3];

    float ty = (float)j / 223.f;
    float ys = (float)y0 + ty * (float)(y1 - y0 - 1);
    int   y0i = (int)floorf(ys);
    int   y1i = min(y0i + 1, 895);
    float wy  = ys - (float)y0i;

    float tx = (float)i / 223.f;
    float xs = (float)x0 + tx * (float)(x1 - x0 - 1);
    int   x0i = (int)floorf(xs);
    int   x1i = min(x0i + 1, 895);
    float wx  = xs - (float)x0i;

    int b  = crop / 6;
    int ya = y0i - PADC, yb = y1i - PADC;
    int xa = x0i - PADC, xb = x1i - PADC;
    bool vya = (unsigned)ya < 448u, vyb = (unsigned)yb < 448u;
    bool vxa = (unsigned)xa < 448u, vxb = (unsigned)xb < 448u;

#pragma unroll
    for (int c = 0; c < 3; ++c) {
        const float* img = x + ((size_t)(b * 3 + c)) * 448 * 448;
        float tl = (vya && vxa) ? __ldg(img + ya * 448 + xa) : 0.f;
        float tr = (vya && vxb) ? __ldg(img + ya * 448 + xb) : 0.f;
        float bl = (vyb && vxa) ? __ldg(img + yb * 448 + xa) : 0.f;
        float br = (vyb && vxb) ? __ldg(img + yb * 448 + xb) : 0.f;
        float v = tl * (1.f - wy) * (1.f - wx)
                + tr * (1.f - wy) * wx
                + bl * wy * (1.f - wx)
                + br * wy * wx;
        out[(((size_t)(crop * 3 + c)) * 224 + j) * 224 + i] = v;
    }
}

// ---------------- launch ----------------
extern "C" void kernel_launch(void* const* d_in, const int* in_sizes, int n_in,
                              void* d_out, int out_size)
{
    const float* x    = (const float*)d_in[0];
    const float* rpn  = (const float*)d_in[1];
    const int*   anch = (const int*)  d_in[2];
    const float* w1   = (const float*)d_in[3];
    const float* b1   = (const float*)d_in[4];
    const float* w2   = (const float*)d_in[5];
    const float* b2   = (const float*)d_in[6];
    const float* w3   = (const float*)d_in[7];
    const float* b3   = (const float*)d_in[8];
    const float* tw1  = (const float*)d_in[9];
    const float* tb1  = (const float*)d_in[10];
    const float* tw2  = (const float*)d_in[11];
    const float* tb2  = (const float*)d_in[12];
    const float* tw3  = (const float*)d_in[13];
    const float* tb3  = (const float*)d_in[14];
    float* out = (float*)d_out;

    const size_t OFF_IDX  = (size_t)Bsz * ANCH;
    const size_t OFF_PROB = OFF_IDX + Bsz * TOPN;
    const size_t OFF_IMG  = OFF_PROB + Bsz * TOPN;

    // prep (slots 1-3) -> conv1_mma at profiled slot 4
    k_wtap<<<dim3(8, 128), 256>>>(w1);
    k_rzero<<<(int)(((size_t)Bsz * RSTR * C_IN / 8 + 255) / 256), 256>>>();
    k_rT<<<dim3(7, 64, 16), dim3(32, 8)>>>(rpn);

    cudaFuncSetAttribute(conv1_mma, cudaFuncAttributeMaxDynamicSharedMemorySize,
                         CONV1_SMEM);
    conv1_mma<<<dim3(16, SPLK), 512, CONV1_SMEM>>>();
    conv1_finish<<<(OC * N1 / 4 + 255) / 256, 256>>>(b1);

    conv2_gemm<<<dim3(16, 8), 256>>>(w2);
    conv2_finish<<<(Bsz * OC * 49 + 255) / 256, 256>>>(b2);

    conv3_gemm<<<dim3(16, 8), 256>>>(w3);
    conv3_finish<<<(Bsz * OC * 16 + 255) / 256, 256>>>(b3);

    tidy_k<<<(Bsz * ANCH + 255) / 256, 256>>>(tw1, tb1, tw2, tb2, tw3, tb3, out);
    nms_k<<<Bsz, 256>>>(out, anch, out + OFF_IDX, out + OFF_PROB);
    crop_k<<<dim3(96, 224), 224>>>(x, anch, out + OFF_IMG);
}

// round 17
// speedup vs baseline: 1.6207x; 1.1080x over previous
#include <cuda_runtime.h>
#include <cuda_fp16.h>
#include <math.h>
#include <stdint.h>

#define Bsz   16
#define ANCH  1614
#define TOPN  6
#define PADC  224
#define C_IN  2048
#define P1    196
#define OC    128
#define K1    18432
#define N1    3136
#define SPLK  9
#define RSTR  304          // padded rows per image (256 grid + 48 guard)

// ---------------- device scratch ----------------
__device__ float   g_part1[SPLK][OC][N1];
__device__ __half  g_wr[9*OC*C_IN];           // W per-tap [tap][oc][ic], single fp16 limb
__device__ __half  g_rp[Bsz*RSTR*C_IN];       // padded activations, single fp16 limb
__device__ float   g_d1[Bsz*OC*P1];
__device__ float   g2_part[8][OC][Bsz*64];
__device__ float   g_d2[Bsz*OC*49];
__device__ float   g3_part[8][OC][Bsz*16];
__device__ float   g_d3[Bsz*OC*16];
__device__ int     g_topidx[Bsz*TOPN];

// ---------------- helpers ----------------
__device__ __forceinline__ uint32_t smem_u32(const void* p) {
    uint32_t a;
    asm("{ .reg .u64 t; cvta.to.shared.u64 t, %1; cvt.u32.u64 %0, t; }" : "=r"(a) : "l"(p));
    return a;
}
__device__ __forceinline__ void ldsm4(uint32_t* r, uint32_t addr) {
    asm volatile("ldmatrix.sync.aligned.m8n8.x4.shared.b16 {%0,%1,%2,%3}, [%4];"
                 : "=r"(r[0]), "=r"(r[1]), "=r"(r[2]), "=r"(r[3]) : "r"(addr));
}
__device__ __forceinline__ void mma_f16(float* c, const uint32_t* a, uint32_t b0, uint32_t b1) {
    asm volatile(
        "mma.sync.aligned.m16n8k16.row.col.f32.f16.f16.f32 "
        "{%0,%1,%2,%3}, {%4,%5,%6,%7}, {%8,%9}, {%0,%1,%2,%3};"
        : "+f"(c[0]), "+f"(c[1]), "+f"(c[2]), "+f"(c[3])
        : "r"(a[0]), "r"(a[1]), "r"(a[2]), "r"(a[3]), "r"(b0), "r"(b1));
}
#define CPA(dst, src) \
    asm volatile("cp.async.cg.shared.global [%0], [%1], 16;" \
        :: "r"(dst), "l"(src) : "memory")
#define CPA_COMMIT() asm volatile("cp.async.commit_group;" ::: "memory")
#define CPA_WAIT0()  asm volatile("cp.async.wait_group 0;" ::: "memory")

// ---------------- fused prep kernel: wtap | rzero | rT (disjoint writes) -------------
#define WT_B  1024
#define RZ_B  4864     // 16*304*2048/8 / 256
#define RT_B  7168     // 7*64*16
__global__ void k_prep(const float* __restrict__ w, const float* __restrict__ r) {
    __shared__ float tile[32][33];
    const int bx  = blockIdx.x;
    const int tid = threadIdx.x;

    if (bx < WT_B) {
        // ---- weight fp16 conversion: [oc][ic][9] -> [tap][oc][ic] ----
        int ic = (bx & 7) * 256 + tid;
        int oc = bx >> 3;
        const float* src = w + (size_t)oc * K1 + (size_t)ic * 9;
        float v[9];
#pragma unroll
        for (int t = 0; t < 9; ++t) v[t] = src[t];
#pragma unroll
        for (int t = 0; t < 9; ++t)
            g_wr[((size_t)t * OC + oc) * C_IN + ic] = __float2half_rn(v[t]);
    } else if (bx < WT_B + RZ_B) {
        // ---- zero-fill pad rows of padded activation grid ----
        size_t i = (size_t)(bx - WT_B) * 256 + tid;   // uint4 index
        size_t elem = i * 8;
        int rowg = (int)(elem / C_IN);
        int row  = rowg % RSTR;
        int y = row >> 4, x = row & 15;
        bool pad = (row >= 256) || (y == 0) || (y == 15) || (x == 0) || (x == 15);
        if (pad) ((uint4*)g_rp)[i] = make_uint4(0, 0, 0, 0);
    } else {
        // ---- transpose interior: [b][ic][196] -> padded [b][(y+1)*16+(x+1)][ic] ----
        int r3  = bx - (WT_B + RZ_B);
        int p0  = (r3 % 7) * 32;
        int ic0 = ((r3 / 7) & 63) * 32;
        int b   = r3 / 448;
        int tx  = tid & 31;
        int ty  = tid >> 5;
        const float* src = r + ((size_t)b * C_IN + ic0) * P1 + p0;
#pragma unroll
        for (int i = 0; i < 4; ++i) {
            int icr = ty + i * 8;
            int p = p0 + tx;
            tile[icr][tx] = (p < P1) ? src[icr * P1 + tx] : 0.f;
        }
        __syncthreads();
#pragma unroll
        for (int i = 0; i < 4; ++i) {
            int p  = p0 + ty + i * 8;
            int ic = ic0 + tx;
            if (p < P1) {
                float v = tile[tx][ty + i * 8];
                int prow = ((p / 14) + 1) * 16 + (p % 14) + 1;
                g_rp[((size_t)b * RSTR + prow) * C_IN + ic] = __float2half_rn(v);
            }
        }
    }
}

// ---------------- conv1: padded-B tap-reuse fp16 single-limb mma.sync GEMM ----------
#define A_ROWB 80
#define A_STG  10240          // 128 rows * 80, 1 limb
#define B_BASE 81920          // after 8 A stages
#define B_ROWS 296
#define B_STG  23680          // 296 * 80, single limb
#define CONV1_SMEM (B_BASE + 2*B_STG)   // 129280

__global__ __launch_bounds__(512, 1)
void conv1_mma(void)
{
    extern __shared__ __align__(256) char sm[];
    const uint32_t smb = smem_u32(sm);
    const int tid  = threadIdx.x;
    const int wid  = tid >> 5;
    const int lane = tid & 31;
    const int bImg = blockIdx.x;        // image 0..15
    const int spl  = blockIdx.y;        // 0..8

    const int u0   = spl * 64;
    const int uend = u0 + 64;
    const int lastBlk = (uend - 1) / 9;

    const int rowA = tid >> 2;
    const int qA   = tid & 3;
    const uint32_t aOff = (uint32_t)(rowA * A_ROWB + qA * 16);

    const int wm = wid & 3;
    const int wn = wid >> 2;
    const uint32_t aLd = smb + (uint32_t)((wm * 32 + (lane & 15)) * A_ROWB + (lane >> 4) * 16);
    const uint32_t bLd = smb + B_BASE +
        (uint32_t)((wn * 64 + (lane & 7) + ((lane >> 4) & 1) * 8) * A_ROWB + ((lane >> 3) & 1) * 16);

    float acc[2][8][4];
#pragma unroll
    for (int mi = 0; mi < 2; ++mi)
#pragma unroll
        for (int j = 0; j < 8; ++j)
#pragma unroll
            for (int q = 0; q < 4; ++q) acc[mi][j][q] = 0.f;

    auto issueA = [&](int tap, int blk, int stage) {
        const size_t srcIdx = (((size_t)tap * OC + rowA) * C_IN) + blk * 32 + qA * 8;
        CPA(smb + (uint32_t)stage * A_STG + aOff, g_wr + srcIdx);
    };
    auto issueB = [&](int blk, int stage) {
        const uint32_t base = smb + B_BASE + (uint32_t)stage * B_STG;
        const size_t gbase = (size_t)bImg * RSTR * C_IN + blk * 32;
#pragma unroll
        for (int i = 0; i < 3; ++i) {
            int op = tid + i * 512;
            if (op < B_ROWS * 4) {
                int row = op >> 2;
                int q   = op & 3;
                CPA(base + row * A_ROWB + q * 16, g_rp + gbase + (size_t)row * C_IN + q * 8);
            }
        }
    };

    auto computeU = [&](int tap, int blk, int astage) {
        const int ky = (tap >= 6) ? 2 : ((tap >= 3) ? 1 : 0);
        const uint32_t delta = (uint32_t)(tap + ky * 13) * A_ROWB;
        const uint32_t aCur = (uint32_t)astage * A_STG;
        const uint32_t bCur = (uint32_t)(blk & 1) * B_STG;
#pragma unroll
        for (int kf = 0; kf < 2; ++kf) {
            uint32_t ah[2][4];
            ldsm4(ah[0], aLd + aCur + kf * 32);
            ldsm4(ah[1], aLd + aCur + kf * 32 + 16 * A_ROWB);
#pragma unroll
            for (int jp = 0; jp < 4; ++jp) {
                uint32_t bh[4];
                ldsm4(bh, bLd + bCur + delta + jp * (16 * A_ROWB) + kf * 32);
                mma_f16(acc[0][jp*2],   ah[0], bh[0], bh[1]);
                mma_f16(acc[0][jp*2+1], ah[0], bh[2], bh[3]);
                mma_f16(acc[1][jp*2],   ah[1], bh[0], bh[1]);
                mma_f16(acc[1][jp*2+1], ah[1], bh[2], bh[3]);
            }
        }
    };

    const int blk0 = u0 / 9;
    const int tap0 = u0 - blk0 * 9;
    issueB(blk0, blk0 & 1);
    if (tap0 > 4 && blk0 + 1 <= lastBlk) issueB(blk0 + 1, (blk0 + 1) & 1);
    {
        int tj = tap0, bj = blk0;
#pragma unroll
        for (int j = 0; j < 4; ++j) {
            issueA(tj, bj, (u0 + j) & 7);
            if (++tj == 9) { tj = 0; ++bj; }
        }
    }
    CPA_COMMIT();

    int tc = tap0 + 4, bc = blk0;
    if (tc >= 9) { tc -= 9; ++bc; }

    int tapu = tap0, blku = blk0;
    for (int p = 0; p < 16; ++p) {
        const int u = u0 + 4 * p;
        CPA_WAIT0();
        __syncthreads();

        bool any = false;
#pragma unroll
        for (int j = 0; j < 4; ++j) {
            if (u + 4 + j < uend) {
                issueA(tc, bc, (u + 4 + j) & 7);
                if (++tc == 9) { tc = 0; ++bc; }
                any = true;
            }
        }
        {
            int tq = tapu, bq = blku;
#pragma unroll
            for (int j = 0; j < 4; ++j) {
                if (tq == 4 && bq + 1 <= lastBlk) {
                    issueB(bq + 1, (bq + 1) & 1);
                    any = true;
                }
                if (++tq == 9) { tq = 0; ++bq; }
            }
        }
        if (any) CPA_COMMIT();

#pragma unroll
        for (int j = 0; j < 4; ++j) {
            computeU(tapu, blku, (u + j) & 7);
            if (++tapu == 9) { tapu = 0; ++blku; }
        }
    }

#pragma unroll
    for (int mi = 0; mi < 2; ++mi) {
        const int r0 = wm * 32 + mi * 16 + (lane >> 2);
#pragma unroll
        for (int j = 0; j < 8; ++j) {
            const int c0 = wn * 64 + j * 8 + (lane & 3) * 2;
            const int oy = c0 >> 4;
            const int ox = c0 & 15;
            if (oy < 14) {
                if (ox < 14) {
                    int n = bImg * 196 + oy * 14 + ox;
                    g_part1[spl][r0][n]     = acc[mi][j][0];
                    g_part1[spl][r0 + 8][n] = acc[mi][j][2];
                }
                if (ox + 1 < 14) {
                    int n = bImg * 196 + oy * 14 + ox + 1;
                    g_part1[spl][r0][n]     = acc[mi][j][1];
                    g_part1[spl][r0 + 8][n] = acc[mi][j][3];
                }
            }
        }
    }
}

__global__ void conv1_finish(const float* __restrict__ bias)
{
    int i = blockIdx.x * 256 + threadIdx.x;   // float4 index
    if (i >= OC * N1 / 4) return;
    int e  = i << 2;
    int oc = e / N1;
    int n  = e - oc * N1;
    float4 s = make_float4(0.f, 0.f, 0.f, 0.f);
    const float* base = &g_part1[0][0][0];
#pragma unroll
    for (int k = 0; k < SPLK; ++k) {
        float4 p = *(const float4*)(base + (size_t)k * OC * N1 + e);
        s.x += p.x; s.y += p.y; s.z += p.z; s.w += p.w;
    }
    float bb = bias[oc];
    s.x = fmaxf(s.x + bb, 0.f);
    s.y = fmaxf(s.y + bb, 0.f);
    s.z = fmaxf(s.z + bb, 0.f);
    s.w = fmaxf(s.w + bb, 0.f);
    int b = n / P1;
    int p = n - b * P1;
    *(float4*)&g_d1[(size_t)b * OC * P1 + oc * P1 + p] = s;
}

// ---------------- conv2: 128->128 3x3 s2 p1 (14->7), split-K GEMM ----------------
__global__ __launch_bounds__(256, 2)
void conv2_gemm(const float* __restrict__ w)
{
    __shared__ __align__(16) float As[16][128];
    __shared__ __align__(16) float Bs[16][64];

    const int b   = blockIdx.x;
    const int spl = blockIdx.y;
    const int tid = threadIdx.x;
    const int k0b = spl * 144;

    const int ocA = tid >> 1;
    const int khA = (tid & 1) * 8;
    const float* wA = w + (size_t)ocA * 1152 + khA;

    const int kkB = tid >> 4;
    const int nB  = (tid & 15) << 2;
    const float* src = g_d1 + (size_t)b * OC * P1;
    int noy[4], nox[4]; bool nok[4];
#pragma unroll
    for (int u = 0; u < 4; ++u) {
        int n = nB + u;
        nok[u] = n < 49;
        int nn = nok[u] ? n : 0;
        noy[u] = nn / 7;
        nox[u] = nn - (nn / 7) * 7;
    }

    const int tm4 = (tid & 15) << 2;
    const int tn4 = (tid >> 4) << 2;

    float acc[8][4];
#pragma unroll
    for (int i = 0; i < 8; ++i)
#pragma unroll
        for (int j = 0; j < 4; ++j) acc[i][j] = 0.f;

    for (int it = 0; it < 9; ++it) {
        int k0 = k0b + it * 16;
        float4 a0 = *(const float4*)(wA + k0);
        float4 a1 = *(const float4*)(wA + k0 + 4);
        float bv[4];
        {
            int k  = k0 + kkB;
            int ic = k / 9;
            int r  = k - ic * 9;
            int ky = r / 3;
            int kx = r - ky * 3;
#pragma unroll
            for (int u = 0; u < 4; ++u) {
                int iy = 2 * noy[u] + ky - 1;
                int ix = 2 * nox[u] + kx - 1;
                bool ok = nok[u] && ((unsigned)iy < 14u) && ((unsigned)ix < 14u);
                bv[u] = ok ? __ldg(src + ic * P1 + iy * 14 + ix) : 0.f;
            }
        }
        __syncthreads();
        As[khA+0][ocA] = a0.x; As[khA+1][ocA] = a0.y;
        As[khA+2][ocA] = a0.z; As[khA+3][ocA] = a0.w;
        As[khA+4][ocA] = a1.x; As[khA+5][ocA] = a1.y;
        As[khA+6][ocA] = a1.z; As[khA+7][ocA] = a1.w;
        *(float4*)&Bs[kkB][nB] = make_float4(bv[0], bv[1], bv[2], bv[3]);
        __syncthreads();

#pragma unroll
        for (int kk = 0; kk < 16; ++kk) {
            float4 q0 = *(const float4*)&As[kk][tm4];
            float4 q1 = *(const float4*)&As[kk][64 + tm4];
            float4 bq = *(const float4*)&Bs[kk][tn4];
            float aa[8] = {q0.x, q0.y, q0.z, q0.w, q1.x, q1.y, q1.z, q1.w};
            float bb[4] = {bq.x, bq.y, bq.z, bq.w};
#pragma unroll
            for (int i = 0; i < 8; ++i)
#pragma unroll
                for (int j = 0; j < 4; ++j)
                    acc[i][j] += aa[i] * bb[j];
        }
    }

#pragma unroll
    for (int i = 0; i < 4; ++i) {
        float4 v0 = make_float4(acc[i][0],   acc[i][1],   acc[i][2],   acc[i][3]);
        float4 v1 = make_float4(acc[i+4][0], acc[i+4][1], acc[i+4][2], acc[i+4][3]);
        *(float4*)&g2_part[spl][tm4 + i     ][b * 64 + tn4] = v0;
        *(float4*)&g2_part[spl][64 + tm4 + i][b * 64 + tn4] = v1;
    }
}

__global__ void conv2_finish(const float* __restrict__ bias)
{
    int i = blockIdx.x * 256 + threadIdx.x;
    if (i >= Bsz * OC * 49) return;
    int b  = i / (OC * 49);
    int r  = i - b * (OC * 49);
    int oc = r / 49;
    int p  = r - oc * 49;
    float s = bias[oc];
#pragma unroll
    for (int k = 0; k < 8; ++k) s += g2_part[k][oc][b * 64 + p];
    g_d2[(size_t)b * OC * 49 + oc * 49 + p] = fmaxf(s, 0.f);
}

// ---------------- conv3: 128->128 3x3 s2 p1 (7->4), split-K GEMM ----------------
__global__ __launch_bounds__(256, 2)
void conv3_gemm(const float* __restrict__ w)
{
    __shared__ __align__(16) float As[16][128];
    __shared__ float Bs[16][16];

    const int b   = blockIdx.x;
    const int spl = blockIdx.y;
    const int tid = threadIdx.x;
    const int k0b = spl * 144;

    const int ocA = tid >> 1;
    const int khA = (tid & 1) * 8;
    const float* wA = w + (size_t)ocA * 1152 + khA;

    const int kkB = tid >> 4;
    const int nnB = tid & 15;
    const int oyB = nnB >> 2, oxB = nnB & 3;
    const float* src = g_d2 + (size_t)b * OC * 49;

    const int tm4 = (tid & 15) << 2;
    const int tn  = tid >> 4;

    float acc[8];
#pragma unroll
    for (int i = 0; i < 8; ++i) acc[i] = 0.f;

    for (int it = 0; it < 9; ++it) {
        int k0 = k0b + it * 16;
        float4 a0 = *(const float4*)(wA + k0);
        float4 a1 = *(const float4*)(wA + k0 + 4);
        float bv;
        {
            int k  = k0 + kkB;
            int ic = k / 9;
            int r  = k - ic * 9;
            int ky = r / 3;
            int kx = r - ky * 3;
            int iy = 2 * oyB + ky - 1;
            int ix = 2 * oxB + kx - 1;
            bool ok = ((unsigned)iy < 7u) && ((unsigned)ix < 7u);
            bv = ok ? __ldg(src + ic * 49 + iy * 7 + ix) : 0.f;
        }
        __syncthreads();
        As[khA+0][ocA] = a0.x; As[khA+1][ocA] = a0.y;
        As[khA+2][ocA] = a0.z; As[khA+3][ocA] = a0.w;
        As[khA+4][ocA] = a1.x; As[khA+5][ocA] = a1.y;
        As[khA+6][ocA] = a1.z; As[khA+7][ocA] = a1.w;
        Bs[kkB][nnB] = bv;
        __syncthreads();

#pragma unroll
        for (int kk = 0; kk < 16; ++kk) {
            float4 q0 = *(const float4*)&As[kk][tm4];
            float4 q1 = *(const float4*)&As[kk][64 + tm4];
            float bb = Bs[kk][tn];
            acc[0] += q0.x * bb; acc[1] += q0.y * bb;
            acc[2] += q0.z * bb; acc[3] += q0.w * bb;
            acc[4] += q1.x * bb; acc[5] += q1.y * bb;
            acc[6] += q1.z * bb; acc[7] += q1.w * bb;
        }
    }

#pragma unroll
    for (int i = 0; i < 4; ++i) {
        g3_part[spl][tm4 + i     ][b * 16 + tn] = acc[i];
        g3_part[spl][64 + tm4 + i][b * 16 + tn] = acc[i + 4];
    }
}

__global__ void conv3_finish(const float* __restrict__ bias)
{
    int i = blockIdx.x * 256 + threadIdx.x;
    if (i >= Bsz * OC * 16) return;
    int b  = i / (OC * 16);
    int r  = i - b * (OC * 16);
    int oc = r / 16;
    int p  = r - oc * 16;
    float s = bias[oc];
#pragma unroll
    for (int k = 0; k < 8; ++k) s += g3_part[k][oc][b * 16 + p];
    g_d3[(size_t)b * OC * 16 + oc * 16 + p] = fmaxf(s, 0.f);
}

// ---------------- tidy 1x1 convs -> rpn_score ----------------
__global__ void tidy_k(const float* __restrict__ w1, const float* __restrict__ b1,
                       const float* __restrict__ w2, const float* __restrict__ b2,
                       const float* __restrict__ w3, const float* __restrict__ b3,
                       float* __restrict__ out)
{
    int i = blockIdx.x * 256 + threadIdx.x;
    if (i >= Bsz * ANCH) return;
    int b = i / ANCH;
    int s = i - b * ANCH;

    const float* src; const float* wp; float bias; int p, stride;
    if (s < 1176) {
        int c = s / 196; p = s - c * 196;
        src = g_d1 + (size_t)b * OC * P1; stride = 196;
        wp = w1 + c * 128; bias = b1[c];
    } else if (s < 1470) {
        int ss = s - 1176; int c = ss / 49; p = ss - c * 49;
        src = g_d2 + (size_t)b * OC * 49; stride = 49;
        wp = w2 + c * 128; bias = b2[c];
    } else {
        int ss = s - 1470; int c = ss / 16; p = ss - c * 16;
        src = g_d3 + (size_t)b * OC * 16; stride = 16;
        wp = w3 + c * 128; bias = b3[c];
    }
    float a0 = 0.f, a1 = 0.f, a2 = 0.f, a3 = 0.f;
#pragma unroll 8
    for (int ic = 0; ic < 128; ic += 4) {
        a0 += src[(ic+0) * stride + p] * __ldg(wp + ic + 0);
        a1 += src[(ic+1) * stride + p] * __ldg(wp + ic + 1);
        a2 += src[(ic+2) * stride + p] * __ldg(wp + ic + 2);
        a3 += src[(ic+3) * stride + p] * __ldg(wp + ic + 3);
    }
    out[(size_t)b * ANCH + s] = bias + ((a0 + a1) + (a2 + a3));
}

// ---------------- hard NMS top-6 per batch (shuffle argmax) ----------------
__global__ void nms_k(const float* __restrict__ scores, const int* __restrict__ anchors,
                      float* __restrict__ out_idx, float* __restrict__ out_prob)
{
    __shared__ float sc[ANCH];
    __shared__ float bx0[ANCH], bx1[ANCH], bx2[ANCH], bx3[ANCH];
    __shared__ float rv[8];
    __shared__ int   ri[8];
    __shared__ int   selj;
    __shared__ int   sel[TOPN];

    const int b = blockIdx.x, tid = threadIdx.x;
    const int lane = tid & 31, wrp = tid >> 5;
    for (int i = tid; i < ANCH; i += 256) {
        sc[i]  = scores[(size_t)b * ANCH + i];
        int4 a = *(const int4*)&anchors[i * 4];
        bx0[i] = (float)a.x; bx1[i] = (float)a.y;
        bx2[i] = (float)a.z; bx3[i] = (float)a.w;
    }
    __syncthreads();

    for (int t = 0; t < TOPN; ++t) {
        float bv = -INFINITY; int bi = ANCH;
        for (int i = tid; i < ANCH; i += 256) {
            float v = sc[i];
            if (v > bv) { bv = v; bi = i; }
        }
        // warp reduce (max value, smallest index on ties)
#pragma unroll
        for (int off = 16; off > 0; off >>= 1) {
            float ov = __shfl_down_sync(0xFFFFFFFFu, bv, off);
            int   oi = __shfl_down_sync(0xFFFFFFFFu, bi, off);
            if (ov > bv || (ov == bv && oi < bi)) { bv = ov; bi = oi; }
        }
        if (lane == 0) { rv[wrp] = bv; ri[wrp] = bi; }
        __syncthreads();
        if (tid == 0) {
            float fv = rv[0]; int fi = ri[0];
#pragma unroll
            for (int k = 1; k < 8; ++k) {
                if (rv[k] > fv || (rv[k] == fv && ri[k] < fi)) { fv = rv[k]; fi = ri[k]; }
            }
            selj = fi;
            sel[t] = fi;
        }
        __syncthreads();
        int j = selj;

        float by0 = bx0[j], by1 = bx1[j], by2 = bx2[j], by3 = bx3[j];
        float a1 = (by2 - by0) * (by3 - by1);
        for (int i = tid; i < ANCH; i += 256) {
            float yy0 = fmaxf(by0, bx0[i]);
            float xx0 = fmaxf(by1, bx1[i]);
            float yy1 = fminf(by2, bx2[i]);
            float xx1 = fminf(by3, bx3[i]);
            float inter = fmaxf(yy1 - yy0, 0.f) * fmaxf(xx1 - xx0, 0.f);
            float a2 = (bx2[i] - bx0[i]) * (bx3[i] - bx1[i]);
            float iou = inter / (a1 + a2 - inter);
            if (iou > 0.25f) sc[i] = -INFINITY;
        }
        __syncthreads();
    }

    if (tid < TOPN) {
        int j = sel[tid];
        out_idx[b * TOPN + tid]  = (float)j;
        out_prob[b * TOPN + tid] = scores[(size_t)b * ANCH + j];
        g_topidx[b * TOPN + tid] = j;
    }
}

// ---------------- bilinear crop-resize 224x224, 8 rows per block ----------------
__global__ void crop_k(const float* __restrict__ x, const int* __restrict__ anchors,
                       float* __restrict__ out)
{
    const int crop = blockIdx.x;
    const int j0   = blockIdx.y * 8;
    const int i    = threadIdx.x;
    const int idx  = g_topidx[crop];
    const int y0 = anchors[idx * 4 + 0];
    const int x0 = anchors[idx * 4 + 1];
    const int y1 = anchors[idx * 4 + 2];
    const int x1 = anchors[idx * 4 + 3];
    const int b  = crop / 6;

    // per-column interpolation constants (reused across 8 rows)
    float tx = (float)i / 223.f;
    float xs = (float)x0 + tx * (float)(x1 - x0 - 1);
    int   x0i = (int)floorf(xs);
    int   x1i = min(x0i + 1, 895);
    float wx  = xs - (float)x0i;
    int xa = x0i - PADC, xb = x1i - PADC;
    bool vxa = (unsigned)xa < 448u, vxb = (unsigned)xb < 448u;

#pragma unroll
    for (int jj = 0; jj < 8; ++jj) {
        const int j = j0 + jj;
        float ty = (float)j / 223.f;
        float ys = (float)y0 + ty * (float)(y1 - y0 - 1);
        int   y0i = (int)floorf(ys);
        int   y1i = min(y0i + 1, 895);
        float wy  = ys - (float)y0i;
        int ya = y0i - PADC, yb = y1i - PADC;
        bool vya = (unsigned)ya < 448u, vyb = (unsigned)yb < 448u;

#pragma unroll
        for (int c = 0; c < 3; ++c) {
            const float* img = x + ((size_t)(b * 3 + c)) * 448 * 448;
            float tl = (vya && vxa) ? __ldg(img + ya * 448 + xa) : 0.f;
            float tr = (vya && vxb) ? __ldg(img + ya * 448 + xb) : 0.f;
            float bl = (vyb && vxa) ? __ldg(img + yb * 448 + xa) : 0.f;
            float br = (vyb && vxb) ? __ldg(img + yb * 448 + xb) : 0.f;
            float v = tl * (1.f - wy) * (1.f - wx)
                    + tr * (1.f - wy) * wx
                    + bl * wy * (1.f - wx)
                    + br * wy * wx;
            out[(((size_t)(crop * 3 + c)) * 224 + j) * 224 + i] = v;
        }
    }
}

// ---------------- launch ----------------
extern "C" void kernel_launch(void* const* d_in, const int* in_sizes, int n_in,
                              void* d_out, int out_size)
{
    const float* x    = (const float*)d_in[0];
    const float* rpn  = (const float*)d_in[1];
    const int*   anch = (const int*)  d_in[2];
    const float* w1   = (const float*)d_in[3];
    const float* b1   = (const float*)d_in[4];
    const float* w2   = (const float*)d_in[5];
    const float* b2   = (const float*)d_in[6];
    const float* w3   = (const float*)d_in[7];
    const float* b3   = (const float*)d_in[8];
    const float* tw1  = (const float*)d_in[9];
    const float* tb1  = (const float*)d_in[10];
    const float* tw2  = (const float*)d_in[11];
    const float* tb2  = (const float*)d_in[12];
    const float* tw3  = (const float*)d_in[13];
    const float* tb3  = (const float*)d_in[14];
    float* out = (float*)d_out;

    const size_t OFF_IDX  = (size_t)Bsz * ANCH;
    const size_t OFF_PROB = OFF_IDX + Bsz * TOPN;
    const size_t OFF_IMG  = OFF_PROB + Bsz * TOPN;

    // fused prep (slot 1..3 collapsed into 1) -> conv1_mma at slot 2
    k_prep<<<WT_B + RZ_B + RT_B, 256>>>(w1, rpn);

    cudaFuncSetAttribute(conv1_mma, cudaFuncAttributeMaxDynamicSharedMemorySize,
                         CONV1_SMEM);
    conv1_mma<<<dim3(16, SPLK), 512, CONV1_SMEM>>>();
    conv1_finish<<<(OC * N1 / 4 + 255) / 256, 256>>>(b1);

    conv2_gemm<<<dim3(16, 8), 256>>>(w2);
    conv2_finish<<<(Bsz * OC * 49 + 255) / 256, 256>>>(b2);

    conv3_gemm<<<dim3(16, 8), 256>>>(w3);
    conv3_finish<<<(Bsz * OC * 16 + 255) / 256, 256>>>(b3);

    tidy_k<<<(Bsz * ANCH + 255) / 256, 256>>>(tw1, tb1, tw2, tb2, tw3, tb3, out);
    nms_k<<<Bsz, 256>>>(out, anch, out + OFF_IDX, out + OFF_PROB);
    crop_k<<<dim3(96, 28), 224>>>(x, anch, out + OFF_IMG);
}